// round 9
// baseline (speedup 1.0000x reference)
#include <cuda_runtime.h>

#define MAX_SEG    4096
#define C_PER_SEG  4096          // per-segment index capacity (mean load ~49)
#define CHUNK      512
#define NBLK       1776          // 148 SMs x 12 blocks (16/SM guaranteed by launch_bounds)
#define NTHR       128

// Monotonic counters: never reset; each launch consumes an exact, fixed number
// of tickets, so epoch arithmetic is deterministic across graph replays.
__device__ unsigned int g_bar;          // barrier tickets: NBLK per launch
__device__ unsigned int g_work;         // work tickets: (n_seg + NBLK) per launch
__device__ int g_cursor[MAX_SEG];       // zeroed by phase 2 of the same launch
__device__ int g_nidx[MAX_SEG * C_PER_SEG];   // 64 MB strided CSR

__global__ void __launch_bounds__(NTHR, 16)   // forces regs <= 32 => 16 blocks/SM possible
k_fused(const float* __restrict__ x, const void* __restrict__ labels,
        float* __restrict__ out, int dim, int n, int n_seg) {
    int tid = threadIdx.x;
    int dim4 = dim >> 2;               // 120 for dim=480

    __shared__ int sh[CHUNK];
    __shared__ int sh_seg;
    __shared__ unsigned int sh_epoch;

    // ---- dtype detect (block-local, branch-uniform) -----------------------
    // View labels as int32 words. int64 labels (< n_seg) have all odd words
    // zero; int32 labels have label values in odd words (nonzero among 128
    // samples w.p. 1-(1/4096)^128). Words [0, n) are in-bounds either way.
    const int* w32 = (const int*)labels;
    const long long* w64 = (const long long*)labels;
    int probe = 2 * tid + 1;
    int my = (probe < n) ? (w32[probe] != 0) : 0;
    int det = __syncthreads_or(my);    // 1 => labels are int32

    // ---- phase 1: scatter node indices into strided CSR -------------------
    for (int i = blockIdx.x * NTHR + tid; i < n; i += NBLK * NTHR) {
        int s = det ? w32[i] : (int)w64[i];
        int p = atomicAdd(&g_cursor[s], 1);
        if (p < C_PER_SEG) g_nidx[s * C_PER_SEG + p] = i;
    }

    // ---- grid barrier (ticket-epoch, monotonic, no reset) ------------------
    if (tid == 0) {
        __threadfence();                              // publish scatter writes
        unsigned int t = atomicAdd(&g_bar, 1u);
        unsigned int epoch = t / NBLK;                // same for all blocks this launch
        unsigned int target = (epoch + 1u) * NBLK;
        while (*(volatile unsigned int*)&g_bar < target)
            __nanosleep(64);
        __threadfence();                              // acquire
        sh_epoch = epoch;
    }
    __syncthreads();
    unsigned int work_base = sh_epoch * (unsigned int)(n_seg + NBLK);

    // ---- phase 2: per-segment gather + mean (dynamic scheduling) ----------
    // Each launch consumes exactly n_seg + NBLK work tickets: every success
    // ticket is drawn, and every block terminates on exactly one failing one.
    for (;;) {
        if (tid == 0)
            sh_seg = (int)(atomicAdd(&g_work, 1u) - work_base);
        __syncthreads();
        int seg = sh_seg;
        __syncthreads();
        if (seg >= n_seg) break;

        int cnt = g_cursor[seg];
        float4 acc = make_float4(0.f, 0.f, 0.f, 0.f);

        if (cnt <= C_PER_SEG) {
            const int* idx = g_nidx + seg * C_PER_SEG;
            for (int base = 0; base < cnt; base += CHUNK) {
                int m = min(CHUNK, cnt - base);
                __syncthreads();
                for (int i = tid; i < m; i += NTHR)
                    sh[i] = idx[base + i];
                __syncthreads();

                if (tid < dim4) {
                    int j = 0;
                    for (; j + 8 <= m; j += 8) {
                        float4 v0 = ((const float4*)(x + (size_t)sh[j + 0] * dim))[tid];
                        float4 v1 = ((const float4*)(x + (size_t)sh[j + 1] * dim))[tid];
                        float4 v2 = ((const float4*)(x + (size_t)sh[j + 2] * dim))[tid];
                        float4 v3 = ((const float4*)(x + (size_t)sh[j + 3] * dim))[tid];
                        float4 v4 = ((const float4*)(x + (size_t)sh[j + 4] * dim))[tid];
                        float4 v5 = ((const float4*)(x + (size_t)sh[j + 5] * dim))[tid];
                        float4 v6 = ((const float4*)(x + (size_t)sh[j + 6] * dim))[tid];
                        float4 v7 = ((const float4*)(x + (size_t)sh[j + 7] * dim))[tid];
                        acc.x += ((v0.x + v1.x) + (v2.x + v3.x)) + ((v4.x + v5.x) + (v6.x + v7.x));
                        acc.y += ((v0.y + v1.y) + (v2.y + v3.y)) + ((v4.y + v5.y) + (v6.y + v7.y));
                        acc.z += ((v0.z + v1.z) + (v2.z + v3.z)) + ((v4.z + v5.z) + (v6.z + v7.z));
                        acc.w += ((v0.w + v1.w) + (v2.w + v3.w)) + ((v4.w + v5.w) + (v6.w + v7.w));
                    }
                    for (; j < m; j++) {
                        float4 v = ((const float4*)(x + (size_t)sh[j] * dim))[tid];
                        acc.x += v.x; acc.y += v.y; acc.z += v.z; acc.w += v.w;
                    }
                }
            }
        } else {
            // overflow fallback (never for realistic inputs): scan labels
            for (int i = 0; i < n; i++) {
                int l = det ? w32[i] : (int)w64[i];
                if (l == seg && tid < dim4) {
                    float4 v = ((const float4*)(x + (size_t)i * dim))[tid];
                    acc.x += v.x; acc.y += v.y; acc.z += v.z; acc.w += v.w;
                }
            }
        }

        if (tid < dim4) {
            float inv = 1.0f / (float)max(cnt, 1);
            float4 o;
            o.x = acc.x * inv;
            o.y = acc.y * inv;
            o.z = acc.z * inv;
            o.w = acc.w * inv;
            ((float4*)(out + (size_t)seg * dim))[tid] = o;
        }

        // self-clean this segment's cursor for the next launch (safe: every
        // segment is processed by exactly one block, after the barrier)
        if (tid == NTHR - 1) g_cursor[seg] = 0;
    }
}

// ---------------------------------------------------------------- launch
extern "C" void kernel_launch(void* const* d_in, const int* in_sizes, int n_in,
                              void* d_out, int out_size) {
    const float* x      = (const float*)d_in[0];
    const void*  labels = d_in[1];
    float*       out    = (float*)d_out;

    int n_nodes = in_sizes[1];
    int dim     = in_sizes[0] / n_nodes;      // 480
    int n_seg   = out_size / dim;             // 4096

    k_fused<<<NBLK, NTHR>>>(x, labels, out, dim, n_nodes, n_seg);
}

// round 10
// speedup vs baseline: 1.1074x; 1.1074x over previous
#include <cuda_runtime.h>

#define MAX_SEG    4096
#define C_PER_SEG  512           // per-segment capacity; 8 MB CSR stays L2-resident
#define CHUNK      512

// Scratch starts zeroed (static init) and is re-zeroed at the end of every
// launch sequence (by k_sum), so each graph replay sees clean state.
__device__ int g_cursor[MAX_SEG];
__device__ int g_nidx[MAX_SEG * C_PER_SEG];   // 8 MB strided CSR (L2-resident)
__device__ int g_det;                          // published by k_scatter, read by fallback

// ---------------------------------------------------------------- convert + scatter
// 1 element/thread: scatter is atomic-latency-bound, so maximal thread-level
// parallelism wins (measured: 1-elem ~6us < 2-elem ~9us < 4-elem ~10.5us).
// Dtype detect fused block-locally: view labels as int32 words. int64 labels
// (< n_seg) have all odd words zero; int32 labels have values in odd words
// (nonzero among 256 samples w.p. 1-(1/4096)^256). Words [0, n) are in-bounds
// under both interpretations; probe words are L2-hot after block 0.
__global__ void k_scatter(const void* __restrict__ labels, int n) {
    const int* w = (const int*)labels;
    int tid = threadIdx.x;

    int probe = 2 * tid + 1;                 // odd words 1..511
    int my = (probe < n) ? (w[probe] != 0) : 0;
    int det = __syncthreads_or(my);          // 1 => labels are int32

    if (blockIdx.x == 0 && tid == 0) g_det = det;

    int i = blockIdx.x * blockDim.x + tid;
    if (i < n) {
        int s = det ? w[i] : (int)((const long long*)labels)[i];
        int p = atomicAdd(&g_cursor[s], 1);
        if (p < C_PER_SEG) g_nidx[s * C_PER_SEG + p] = i;
    }
}

// ---------------------------------------------------------------- per-segment gather + mean
// One block per segment (proven 63.9us @ 6.15 TB/s). Threads [0, dim/4) each
// own one float4 column slice; indices staged via shared memory; x8 unroll.
__global__ void __launch_bounds__(128) k_sum(const float* __restrict__ x,
                                             const void* __restrict__ labels,
                                             float* __restrict__ out,
                                             int dim, int n) {
    int seg  = blockIdx.x;
    int tid  = threadIdx.x;
    int dim4 = dim >> 2;               // 120 for dim=480
    int cnt  = g_cursor[seg];

    __shared__ int sh[CHUNK];
    float4 acc = make_float4(0.f, 0.f, 0.f, 0.f);

    if (cnt <= C_PER_SEG) {
        const int* idx = g_nidx + seg * C_PER_SEG;
        for (int base = 0; base < cnt; base += CHUNK) {
            int m = min(CHUNK, cnt - base);
            __syncthreads();
            for (int i = tid; i < m; i += blockDim.x)
                sh[i] = idx[base + i];
            __syncthreads();

            if (tid < dim4) {
                int j = 0;
                for (; j + 8 <= m; j += 8) {
                    float4 v0 = ((const float4*)(x + (size_t)sh[j + 0] * dim))[tid];
                    float4 v1 = ((const float4*)(x + (size_t)sh[j + 1] * dim))[tid];
                    float4 v2 = ((const float4*)(x + (size_t)sh[j + 2] * dim))[tid];
                    float4 v3 = ((const float4*)(x + (size_t)sh[j + 3] * dim))[tid];
                    float4 v4 = ((const float4*)(x + (size_t)sh[j + 4] * dim))[tid];
                    float4 v5 = ((const float4*)(x + (size_t)sh[j + 5] * dim))[tid];
                    float4 v6 = ((const float4*)(x + (size_t)sh[j + 6] * dim))[tid];
                    float4 v7 = ((const float4*)(x + (size_t)sh[j + 7] * dim))[tid];
                    acc.x += ((v0.x + v1.x) + (v2.x + v3.x)) + ((v4.x + v5.x) + (v6.x + v7.x));
                    acc.y += ((v0.y + v1.y) + (v2.y + v3.y)) + ((v4.y + v5.y) + (v6.y + v7.y));
                    acc.z += ((v0.z + v1.z) + (v2.z + v3.z)) + ((v4.z + v5.z) + (v6.z + v7.z));
                    acc.w += ((v0.w + v1.w) + (v2.w + v3.w)) + ((v4.w + v5.w) + (v6.w + v7.w));
                }
                for (; j < m; j++) {
                    float4 v = ((const float4*)(x + (size_t)sh[j] * dim))[tid];
                    acc.x += v.x; acc.y += v.y; acc.z += v.z; acc.w += v.w;
                }
            }
        }
    } else {
        // overflow fallback (P ~ 0 for realistic inputs): scan labels directly
        int det = g_det;
        const int*       w32 = (const int*)labels;
        const long long* w64 = (const long long*)labels;
        for (int i = 0; i < n; i++) {
            int l = det ? w32[i] : (int)w64[i];
            if (l == seg && tid < dim4) {
                float4 v = ((const float4*)(x + (size_t)i * dim))[tid];
                acc.x += v.x; acc.y += v.y; acc.z += v.z; acc.w += v.w;
            }
        }
    }

    if (tid < dim4) {
        float inv = 1.0f / (float)max(cnt, 1);
        float4 o;
        o.x = acc.x * inv;
        o.y = acc.y * inv;
        o.z = acc.z * inv;
        o.w = acc.w * inv;
        ((float4*)(out + (size_t)seg * dim))[tid] = o;
    }

    // self-clean scratch for the next graph replay
    if (tid == 127) g_cursor[seg] = 0;
}

// ---------------------------------------------------------------- launch
extern "C" void kernel_launch(void* const* d_in, const int* in_sizes, int n_in,
                              void* d_out, int out_size) {
    const float* x      = (const float*)d_in[0];
    const void*  labels = d_in[1];
    float*       out    = (float*)d_out;

    int n_nodes = in_sizes[1];
    int dim     = in_sizes[0] / n_nodes;      // 480
    int n_seg   = out_size / dim;             // 4096

    k_scatter<<<(n_nodes + 255) / 256, 256>>>(labels, n_nodes);
    k_sum<<<n_seg, 128>>>(x, labels, out, dim, n_nodes);
}

// round 11
// speedup vs baseline: 1.1423x; 1.0315x over previous
#include <cuda_runtime.h>

#define MAX_SEG    4096
#define C_PER_SEG  4096          // 64 MB strided CSR — measured faster than 8 MB (R7 vs R10)
#define CHUNK      512

// Scratch starts zeroed (static init) and is re-zeroed at the end of every
// launch sequence (by k_sum), so each graph replay sees clean state.
__device__ int g_cursor[MAX_SEG];
__device__ int g_nidx[MAX_SEG * C_PER_SEG];
__device__ int g_det;                          // published by k_scatter, read by fallback

// ---------------------------------------------------------------- convert + scatter
// 1 element/thread: scatter is atomic-latency-bound; max TLP wins (measured
// 1-elem ~6us < 2-elem ~9us < 4-elem ~10.5us). Dtype detect fused block-
// locally: int64 labels (< n_seg) have all odd int32 words zero; int32 labels
// have values in odd words (nonzero among 256 samples w.p. 1-(1/4096)^256).
// Words [0, n) are in-bounds under both interpretations; probes are L2-hot.
__global__ void k_scatter(const void* __restrict__ labels, int n) {
    const int* w = (const int*)labels;
    int tid = threadIdx.x;

    int probe = 2 * tid + 1;                 // odd words 1..511
    int my = (probe < n) ? (w[probe] != 0) : 0;
    int det = __syncthreads_or(my);          // 1 => labels are int32

    if (blockIdx.x == 0 && tid == 0) g_det = det;

    int i = blockIdx.x * blockDim.x + tid;
    if (i < n) {
        int s = det ? w[i] : (int)((const long long*)labels)[i];
        int p = atomicAdd(&g_cursor[s], 1);
        if (p < C_PER_SEG) g_nidx[s * C_PER_SEG + p] = i;
    }
}

// ---------------------------------------------------------------- per-segment gather + mean
// One block per segment (R7 config: 63.9us @ 6.15 TB/s). Threads [0, dim/4)
// each own one float4 column slice; indices staged via shared memory; x8
// unroll for MLP. x is single-use -> __ldcs (evict-first) keeps L2 clean for
// the index stream; output stored with __stcs.
__global__ void __launch_bounds__(128) k_sum(const float* __restrict__ x,
                                             const void* __restrict__ labels,
                                             float* __restrict__ out,
                                             int dim, int n) {
    int seg  = blockIdx.x;
    int tid  = threadIdx.x;
    int dim4 = dim >> 2;               // 120 for dim=480
    int cnt  = g_cursor[seg];

    __shared__ int sh[CHUNK];
    float4 acc = make_float4(0.f, 0.f, 0.f, 0.f);

    if (cnt <= C_PER_SEG) {
        const int* idx = g_nidx + seg * C_PER_SEG;
        for (int base = 0; base < cnt; base += CHUNK) {
            int m = min(CHUNK, cnt - base);
            __syncthreads();
            for (int i = tid; i < m; i += blockDim.x)
                sh[i] = idx[base + i];
            __syncthreads();

            if (tid < dim4) {
                int j = 0;
                for (; j + 8 <= m; j += 8) {
                    float4 v0 = __ldcs((const float4*)(x + (size_t)sh[j + 0] * dim) + tid);
                    float4 v1 = __ldcs((const float4*)(x + (size_t)sh[j + 1] * dim) + tid);
                    float4 v2 = __ldcs((const float4*)(x + (size_t)sh[j + 2] * dim) + tid);
                    float4 v3 = __ldcs((const float4*)(x + (size_t)sh[j + 3] * dim) + tid);
                    float4 v4 = __ldcs((const float4*)(x + (size_t)sh[j + 4] * dim) + tid);
                    float4 v5 = __ldcs((const float4*)(x + (size_t)sh[j + 5] * dim) + tid);
                    float4 v6 = __ldcs((const float4*)(x + (size_t)sh[j + 6] * dim) + tid);
                    float4 v7 = __ldcs((const float4*)(x + (size_t)sh[j + 7] * dim) + tid);
                    acc.x += ((v0.x + v1.x) + (v2.x + v3.x)) + ((v4.x + v5.x) + (v6.x + v7.x));
                    acc.y += ((v0.y + v1.y) + (v2.y + v3.y)) + ((v4.y + v5.y) + (v6.y + v7.y));
                    acc.z += ((v0.z + v1.z) + (v2.z + v3.z)) + ((v4.z + v5.z) + (v6.z + v7.z));
                    acc.w += ((v0.w + v1.w) + (v2.w + v3.w)) + ((v4.w + v5.w) + (v6.w + v7.w));
                }
                for (; j < m; j++) {
                    float4 v = __ldcs((const float4*)(x + (size_t)sh[j] * dim) + tid);
                    acc.x += v.x; acc.y += v.y; acc.z += v.z; acc.w += v.w;
                }
            }
        }
    } else {
        // overflow fallback (P ~ 0 for realistic inputs): scan labels directly
        int det = g_det;
        const int*       w32 = (const int*)labels;
        const long long* w64 = (const long long*)labels;
        for (int i = 0; i < n; i++) {
            int l = det ? w32[i] : (int)w64[i];
            if (l == seg && tid < dim4) {
                float4 v = ((const float4*)(x + (size_t)i * dim))[tid];
                acc.x += v.x; acc.y += v.y; acc.z += v.z; acc.w += v.w;
            }
        }
    }

    if (tid < dim4) {
        float inv = 1.0f / (float)max(cnt, 1);
        float4 o;
        o.x = acc.x * inv;
        o.y = acc.y * inv;
        o.z = acc.z * inv;
        o.w = acc.w * inv;
        __stcs((float4*)(out + (size_t)seg * dim) + tid, o);
    }

    // self-clean scratch for the next graph replay
    if (tid == 127) g_cursor[seg] = 0;
}

// ---------------------------------------------------------------- launch
extern "C" void kernel_launch(void* const* d_in, const int* in_sizes, int n_in,
                              void* d_out, int out_size) {
    const float* x      = (const float*)d_in[0];
    const void*  labels = d_in[1];
    float*       out    = (float*)d_out;

    int n_nodes = in_sizes[1];
    int dim     = in_sizes[0] / n_nodes;      // 480
    int n_seg   = out_size / dim;             // 4096

    k_scatter<<<(n_nodes + 255) / 256, 256>>>(labels, n_nodes);
    k_sum<<<n_seg, 128>>>(x, labels, out, dim, n_nodes);
}